// round 9
// baseline (speedup 1.0000x reference)
#include <cuda_runtime.h>
#include <cuda_fp16.h>
#include <cstdint>
#include <math.h>

// LSTMCell fused via mma.sync fp16 (m16n8k16, f32 accum) GEMMs.
//   gates = [x|h] @ Wt1^T + bias             (K=1024, N=2048)
//   s     = sigmoid([x|me] @ Wt2^T + mb)*me  (K=2048, N=1536)
//   t     = s @ Wt3^T ; LSTM epilogue        (K=1536, N=512)
// 3-stage all-cp.async pipeline, BK=64. Mainloop flattened into 16 (kk,mt)
// units with ldmatrix/MMA interleave (double-buffered fragments).

#define BATCH 16384

// ---------------- scratch (__device__ globals: no allocations allowed) ----
__device__ float  g_gates[(size_t)BATCH * 2048];   // 128 MiB fp32
__device__ __half g_x16[(size_t)BATCH * 512];
__device__ __half g_h16[(size_t)BATCH * 512];
__device__ __half g_me16[(size_t)BATCH * 1536];
__device__ __half g_s16[(size_t)BATCH * 1536];
__device__ __half g_Wt1[(size_t)2048 * 1024];      // [n][k] K-major fp16
__device__ __half g_Wt2[(size_t)1536 * 2048];
__device__ __half g_Wt3[(size_t)512 * 1536];

__device__ __forceinline__ float sigf(float x) { return 1.0f / (1.0f + __expf(-x)); }
__device__ __forceinline__ float tanh_(float x) { return 2.0f * sigf(2.0f * x) - 1.0f; }

__device__ __forceinline__ void mma_f16(float& c0, float& c1, float& c2, float& c3,
                                        uint32_t a0, uint32_t a1, uint32_t a2, uint32_t a3,
                                        uint32_t b0, uint32_t b1) {
    asm volatile(
        "mma.sync.aligned.m16n8k16.row.col.f32.f16.f16.f32 "
        "{%0,%1,%2,%3}, {%4,%5,%6,%7}, {%8,%9}, {%0,%1,%2,%3};"
        : "+f"(c0), "+f"(c1), "+f"(c2), "+f"(c3)
        : "r"(a0), "r"(a1), "r"(a2), "r"(a3), "r"(b0), "r"(b1));
}

__device__ __forceinline__ void ldsm_x4(uint32_t& r0, uint32_t& r1,
                                        uint32_t& r2, uint32_t& r3, uint32_t addr) {
    asm volatile("ldmatrix.sync.aligned.m8n8.x4.shared.b16 {%0,%1,%2,%3}, [%4];"
                 : "=r"(r0), "=r"(r1), "=r"(r2), "=r"(r3) : "r"(addr));
}

#define CP_ASYNC16(dst_u32, src_ptr) \
    asm volatile("cp.async.cg.shared.global [%0], [%1], 16;" \
                 :: "r"(dst_u32), "l"(src_ptr))
#define CP_COMMIT() asm volatile("cp.async.commit_group;")
#define CP_WAIT1()  asm volatile("cp.async.wait_group 1;" ::: "memory")
#define CP_WAIT0()  asm volatile("cp.async.wait_group 0;" ::: "memory")

// ---------------- weight transpose -> fp16 K-major pre-pass ---------------
__device__ __forceinline__ void tr_body(const float* __restrict__ src,
                                        __half* __restrict__ dst,
                                        int C, int dstStride, int bx, int by) {
    __shared__ float t[32][33];
    const int c0 = bx << 5, r0 = by << 5;
    const int tx = threadIdx.x, ty = threadIdx.y;
#pragma unroll
    for (int j = ty; j < 32; j += 8)
        t[j][tx] = src[(size_t)(r0 + j) * C + c0 + tx];
    __syncthreads();
#pragma unroll
    for (int j = ty; j < 32; j += 8)
        dst[(size_t)(c0 + j) * dstStride + r0 + tx] = __float2half_rn(t[tx][j]);
}

__global__ void __launch_bounds__(256) transpose_all(
    const float* __restrict__ W_ih,  const float* __restrict__ W_hh,
    const float* __restrict__ W_memi, const float* __restrict__ W_memh,
    const float* __restrict__ W_memt)
{
    int id = blockIdx.x;
    if (id < 1024)      tr_body(W_ih,   g_Wt1,        2048, 1024, id % 64, id / 64);
    else if (id < 2048) { id -= 1024; tr_body(W_hh,   g_Wt1 + 512, 2048, 1024, id % 64, id / 64); }
    else if (id < 2816) { id -= 2048; tr_body(W_memi, g_Wt2,       1536, 2048, id % 48, id / 48); }
    else if (id < 5120) { id -= 2816; tr_body(W_memh, g_Wt2 + 512, 1536, 2048, id % 48, id / 48); }
    else                { id -= 5120; tr_body(W_memt, g_Wt3,        512, 1536, id % 16, id / 16); }
}

// ---------------- activation fp16 conversion pre-pass ---------------------
__global__ void __launch_bounds__(256) pack_half(
    const float* __restrict__ x, const float* __restrict__ h,
    const float* __restrict__ me)
{
    const int i = blockIdx.x * 256 + threadIdx.x;   // float4 index
    const int N1 = BATCH * 128;
    const int N2 = N1 + BATCH * 128;
    const float* src; __half* dst;
    size_t off;
    if (i < N1)      { off = (size_t)i << 2;        src = x;  dst = g_x16; }
    else if (i < N2) { off = (size_t)(i - N1) << 2; src = h;  dst = g_h16; }
    else             { off = (size_t)(i - N2) << 2; src = me; dst = g_me16; }
    const float4 v = *(const float4*)(src + off);
    const __half2 lo = __floats2half2_rn(v.x, v.y);
    const __half2 hi = __floats2half2_rn(v.z, v.w);
    uint2 u;
    u.x = *(const uint32_t*)&lo;
    u.y = *(const uint32_t*)&hi;
    *(uint2*)(dst + off) = u;
}

// ---------------- main GEMM ------------------------------------------------
// Tile 128x128, BK=64, 8 warps (2M x 4N), warp 64x32 = 4x4 m16n8k16 per kk.
// SMEM per stage: A[128][72] + B[128][72] halves, row 144B. 3 stages.
#define ROWB 144
#define TILE_B (128 * ROWB)
#define STAGE_B (2 * TILE_B)
#define SMEM_BYTES (3 * STAGE_B)    // 110592

template <int MODE>
__global__ void __launch_bounds__(256, 2) mma_gemm(
    const __half* __restrict__ A0, int lda0,
    const __half* __restrict__ A1, int lda1,
    int K0, int K,
    const __half* __restrict__ Wt,
    const float* __restrict__ bias,
    const float* __restrict__ me,
    const float* __restrict__ cin, const float* __restrict__ hin,
    float* __restrict__ outp)
{
    extern __shared__ char smem[];
    const uint32_t sbase = (uint32_t)__cvta_generic_to_shared(smem);
    const int tid = threadIdx.x, wid = tid >> 5, lane = tid & 31;
    const int bm = blockIdx.y << 7, bn = blockIdx.x << 7;
    const int wm = (wid >> 2) << 6;
    const int wn = (wid & 3) << 5;
    const int grp = lane >> 2, qd = lane & 3;

    float acc[4][4][4];
#pragma unroll
    for (int mt = 0; mt < 4; mt++)
#pragma unroll
        for (int nt = 0; nt < 4; nt++)
#pragma unroll
            for (int q = 0; q < 4; q++) acc[mt][nt][q] = 0.0f;

    const int nst = K >> 6;

    // ldmatrix per-lane byte offsets within a stage (kk adds 32B):
    const int l7 = lane & 7;
    const uint32_t a_off =
        (uint32_t)((wm + l7 + (((lane >> 3) & 1) << 3)) * ROWB) +
        (uint32_t)((((lane >> 4) & 1)) << 4);
    const uint32_t b_off = (uint32_t)TILE_B +
        (uint32_t)((wn + (((lane >> 4) & 1) << 3) + l7) * ROWB) +
        (uint32_t)((((lane >> 3) & 1)) << 4);

#define ISSUE_AB(S, BUF) do {                                                   \
    const int _k0 = (S) << 6;                                                   \
    _Pragma("unroll")                                                           \
    for (int t = 0; t < 4; t++) {                                               \
        const int i = tid + (t << 8);                                           \
        const int row = i >> 3, c16 = i & 7;                                    \
        const int ka = _k0 + (c16 << 3);                                        \
        const __half* pa = (ka < K0)                                            \
            ? A0 + (size_t)(bm + row) * lda0 + ka                               \
            : A1 + (size_t)(bm + row) * lda1 + (ka - K0);                       \
        const uint32_t dA = sbase +                                             \
            (uint32_t)((BUF) * STAGE_B + row * ROWB + (c16 << 4));              \
        CP_ASYNC16(dA, pa);                                                     \
        const uint32_t dB = sbase +                                             \
            (uint32_t)((BUF) * STAGE_B + TILE_B + row * ROWB + (c16 << 4));     \
        CP_ASYNC16(dB, Wt + (size_t)(bn + row) * K + ka);                       \
    }                                                                           \
    CP_COMMIT(); } while (0)

    ISSUE_AB(0, 0);
    ISSUE_AB(1, 1);

    uint32_t af[2][4];      // A fragment double buffer (per (kk,mt) unit)
    uint32_t bf[2][8];      // B fragment double buffer (per kk)

#define LDSM_B(BUFI, KK)                                                        \
    do {                                                                        \
        ldsm_x4(bf[BUFI][0], bf[BUFI][1], bf[BUFI][2], bf[BUFI][3],             \
                bbuf + (uint32_t)((KK) * 32));                                  \
        ldsm_x4(bf[BUFI][4], bf[BUFI][5], bf[BUFI][6], bf[BUFI][7],             \
                bbuf + (uint32_t)(16 * ROWB) + (uint32_t)((KK) * 32));          \
    } while (0)
#define LDSM_A(BUFI, KK, MT)                                                    \
    ldsm_x4(af[BUFI][0], af[BUFI][1], af[BUFI][2], af[BUFI][3],                 \
            abuf + (uint32_t)((MT) * (16 * ROWB)) + (uint32_t)((KK) * 32))

    int buf = 0;   // = s % 3
    for (int s = 0; s < nst; s++) {
        if (s + 1 < nst) CP_WAIT1(); else CP_WAIT0();
        __syncthreads();

        const uint32_t abuf = sbase + (uint32_t)(buf * STAGE_B) + a_off;
        const uint32_t bbuf = sbase + (uint32_t)(buf * STAGE_B) + b_off;

        // preload first fragments, then hide their latency under cp.async issue
        LDSM_B(0, 0);
        LDSM_A(0, 0, 0);
        if (s + 2 < nst) {
            const int wbuf = (buf + 2 >= 3) ? buf - 1 : buf + 2;
            ISSUE_AB(s + 2, wbuf);
        }

        // 16 units: (kk,mt); unit u computes with af[u&1], prefetches next.
#pragma unroll
        for (int u = 0; u < 16; u++) {
            const int kk = u >> 2, mt = u & 3;
            const int ca = u & 1, na = ca ^ 1;
            const int cb = kk & 1;
            if (mt < 3)            LDSM_A(na, kk, mt + 1);
            else if (kk < 3)       LDSM_A(na, kk + 1, 0);
            if (mt == 2 && kk < 3) LDSM_B(cb ^ 1, kk + 1);
#pragma unroll
            for (int nt = 0; nt < 4; nt++)
                mma_f16(acc[mt][nt][0], acc[mt][nt][1],
                        acc[mt][nt][2], acc[mt][nt][3],
                        af[ca][0], af[ca][1], af[ca][2], af[ca][3],
                        bf[cb][2 * nt], bf[cb][2 * nt + 1]);
        }
        buf = (buf + 1 >= 3) ? 0 : buf + 1;
    }

    // ---- fused epilogues (c frag rows grp/grp+8, cols 2qd/2qd+1) ----
#pragma unroll
    for (int mt = 0; mt < 4; mt++) {
#pragma unroll
        for (int nt = 0; nt < 4; nt++) {
#pragma unroll
            for (int hrow = 0; hrow < 2; hrow++) {
                const int r = bm + wm + (mt << 4) + grp + (hrow << 3);
                const int cc = bn + wn + (nt << 3) + (qd << 1);
                const float v0 = acc[mt][nt][hrow * 2];
                const float v1 = acc[mt][nt][hrow * 2 + 1];
                if (MODE == 0) {
                    const float2 b2 = *(const float2*)(bias + cc);
                    float2 o = {v0 + b2.x, v1 + b2.y};
                    *(float2*)(g_gates + (size_t)r * 2048 + cc) = o;
                } else if (MODE == 1) {
                    const float2 b2 = *(const float2*)(bias + cc);
                    const float2 m2 = *(const float2*)(me + (size_t)r * 1536 + cc);
                    const __half2 o = __floats2half2_rn(sigf(v0 + b2.x) * m2.x,
                                                        sigf(v1 + b2.y) * m2.y);
                    *(__half2*)(g_s16 + (size_t)r * 1536 + cc) = o;
                } else {
                    const size_t gb = (size_t)r * 2048 + cc;
                    const float2 f2 = *(const float2*)(g_gates + gb);
                    const float2 i2 = *(const float2*)(g_gates + gb + 512);
                    const float2 o2 = *(const float2*)(g_gates + gb + 1024);
                    const float2 g2 = *(const float2*)(g_gates + gb + 1536);
                    const float2 c2 = *(const float2*)(cin + (size_t)r * 512 + cc);
                    const float2 h2 = *(const float2*)(hin + (size_t)r * 512 + cc);
                    float2 oh, oc;
                    {
                        float cn = sigf(f2.x) * c2.x + sigf(i2.x) * tanh_(g2.x) + v0;
                        float hn = sigf(o2.x) * tanh_(cn);
                        oh.x = 0.8f * hn + 0.2f * h2.x;
                        oc.x = 0.8f * cn + 0.2f * c2.x;
                    }
                    {
                        float cn = sigf(f2.y) * c2.y + sigf(i2.y) * tanh_(g2.y) + v1;
                        float hn = sigf(o2.y) * tanh_(cn);
                        oh.y = 0.8f * hn + 0.2f * h2.y;
                        oc.y = 0.8f * cn + 0.2f * c2.y;
                    }
                    *(float2*)(outp + (size_t)r * 512 + cc) = oh;
                    *(float2*)(outp + (size_t)BATCH * 512 + (size_t)r * 512 + cc) = oc;
                }
            }
        }
    }
}

// ---------------- host ----------------------------------------------------
extern "C" void kernel_launch(void* const* d_in, const int* in_sizes, int n_in,
                              void* d_out, int out_size)
{
    const float* x      = (const float*)d_in[0];
    const float* h      = (const float*)d_in[1];
    const float* c      = (const float*)d_in[2];
    const float* me     = (const float*)d_in[3];
    const float* W_ih   = (const float*)d_in[4];
    const float* W_hh   = (const float*)d_in[5];
    const float* bias   = (const float*)d_in[6];
    const float* W_memi = (const float*)d_in[7];
    const float* W_memh = (const float*)d_in[8];
    const float* W_memt = (const float*)d_in[9];
    const float* mem_b  = (const float*)d_in[10];
    float* out = (float*)d_out;

    cudaFuncSetAttribute(mma_gemm<0>, cudaFuncAttributeMaxDynamicSharedMemorySize, SMEM_BYTES);
    cudaFuncSetAttribute(mma_gemm<1>, cudaFuncAttributeMaxDynamicSharedMemorySize, SMEM_BYTES);
    cudaFuncSetAttribute(mma_gemm<2>, cudaFuncAttributeMaxDynamicSharedMemorySize, SMEM_BYTES);

    __half *wt1, *wt2, *wt3, *x16, *h16, *me16, *s16;
    cudaGetSymbolAddress((void**)&wt1, g_Wt1);
    cudaGetSymbolAddress((void**)&wt2, g_Wt2);
    cudaGetSymbolAddress((void**)&wt3, g_Wt3);
    cudaGetSymbolAddress((void**)&x16, g_x16);
    cudaGetSymbolAddress((void**)&h16, g_h16);
    cudaGetSymbolAddress((void**)&me16, g_me16);
    cudaGetSymbolAddress((void**)&s16, g_s16);

    transpose_all<<<5888, dim3(32, 8)>>>(W_ih, W_hh, W_memi, W_memh, W_memt);
    pack_half<<<(BATCH * 640) / 256, 256>>>(x, h, me);

    mma_gemm<0><<<dim3(16, 128), 256, SMEM_BYTES>>>(
        x16, 512, h16, 512, 512, 1024, wt1, bias, nullptr, nullptr, nullptr, nullptr);

    mma_gemm<1><<<dim3(12, 128), 256, SMEM_BYTES>>>(
        x16, 512, me16, 1536, 512, 2048, wt2, mem_b, me, nullptr, nullptr, nullptr);

    mma_gemm<2><<<dim3(4, 128), 256, SMEM_BYTES>>>(
        s16, 1536, s16, 1536, 1536, 1536, wt3, nullptr, nullptr, c, h, out);
}

// round 12
// speedup vs baseline: 1.4350x; 1.4350x over previous
#include <cuda_runtime.h>
#include <cuda_fp16.h>
#include <cstdint>
#include <math.h>

// LSTMCell fused via mma.sync fp16 (m16n8k16, f32 accum) GEMMs.
//   gates = [x|h] @ Wt1^T + bias             (K=1024, N=2048)
//   s     = sigmoid([x|me] @ Wt2^T + mb)*me  (K=2048, N=1536)
//   t     = s @ Wt3^T ; LSTM epilogue        (K=1536, N=512)
// R8 skeleton (3-stage cp.async, BK=64) + kk-level B-fragment prefetch.

#define BATCH 16384

// ---------------- scratch (__device__ globals: no allocations allowed) ----
__device__ float  g_gates[(size_t)BATCH * 2048];   // 128 MiB fp32
__device__ __half g_x16[(size_t)BATCH * 512];
__device__ __half g_h16[(size_t)BATCH * 512];
__device__ __half g_me16[(size_t)BATCH * 1536];
__device__ __half g_s16[(size_t)BATCH * 1536];
__device__ __half g_Wt1[(size_t)2048 * 1024];      // [n][k] K-major fp16
__device__ __half g_Wt2[(size_t)1536 * 2048];
__device__ __half g_Wt3[(size_t)512 * 1536];

__device__ __forceinline__ float sigf(float x) { return 1.0f / (1.0f + __expf(-x)); }
__device__ __forceinline__ float tanh_(float x) { return 2.0f * sigf(2.0f * x) - 1.0f; }

__device__ __forceinline__ void mma_f16(float& c0, float& c1, float& c2, float& c3,
                                        uint32_t a0, uint32_t a1, uint32_t a2, uint32_t a3,
                                        uint32_t b0, uint32_t b1) {
    asm volatile(
        "mma.sync.aligned.m16n8k16.row.col.f32.f16.f16.f32 "
        "{%0,%1,%2,%3}, {%4,%5,%6,%7}, {%8,%9}, {%0,%1,%2,%3};"
        : "+f"(c0), "+f"(c1), "+f"(c2), "+f"(c3)
        : "r"(a0), "r"(a1), "r"(a2), "r"(a3), "r"(b0), "r"(b1));
}

__device__ __forceinline__ void ldsm_x4(uint32_t& r0, uint32_t& r1,
                                        uint32_t& r2, uint32_t& r3, uint32_t addr) {
    asm volatile("ldmatrix.sync.aligned.m8n8.x4.shared.b16 {%0,%1,%2,%3}, [%4];"
                 : "=r"(r0), "=r"(r1), "=r"(r2), "=r"(r3) : "r"(addr));
}

#define CP_ASYNC16(dst_u32, src_ptr) \
    asm volatile("cp.async.cg.shared.global [%0], [%1], 16;" \
                 :: "r"(dst_u32), "l"(src_ptr))
#define CP_COMMIT() asm volatile("cp.async.commit_group;")
#define CP_WAIT1()  asm volatile("cp.async.wait_group 1;" ::: "memory")
#define CP_WAIT0()  asm volatile("cp.async.wait_group 0;" ::: "memory")

// ---------------- merged pre-pass: weight transpose + activation pack -----
__device__ __forceinline__ void tr_body(const float* __restrict__ src,
                                        __half* __restrict__ dst,
                                        int C, int dstStride, int bx, int by) {
    __shared__ float t[32][33];
    const int c0 = bx << 5, r0 = by << 5;
    const int tx = threadIdx.x & 31, ty = threadIdx.x >> 5;
#pragma unroll
    for (int j = ty; j < 32; j += 8)
        t[j][tx] = src[(size_t)(r0 + j) * C + c0 + tx];
    __syncthreads();
#pragma unroll
    for (int j = ty; j < 32; j += 8)
        dst[(size_t)(c0 + j) * dstStride + r0 + tx] = __float2half_rn(t[tx][j]);
}

// grid = 5888 transpose blocks + 40960 pack blocks (256 thr each)
__global__ void __launch_bounds__(256) prepass_all(
    const float* __restrict__ W_ih,  const float* __restrict__ W_hh,
    const float* __restrict__ W_memi, const float* __restrict__ W_memh,
    const float* __restrict__ W_memt,
    const float* __restrict__ x, const float* __restrict__ h,
    const float* __restrict__ me)
{
    int id = blockIdx.x;
    if (id < 5888) {
        if (id < 1024)      tr_body(W_ih,   g_Wt1,        2048, 1024, id % 64, id / 64);
        else if (id < 2048) { id -= 1024; tr_body(W_hh,   g_Wt1 + 512, 2048, 1024, id % 64, id / 64); }
        else if (id < 2816) { id -= 2048; tr_body(W_memi, g_Wt2,       1536, 2048, id % 48, id / 48); }
        else if (id < 5120) { id -= 2816; tr_body(W_memh, g_Wt2 + 512, 1536, 2048, id % 48, id / 48); }
        else                { id -= 5120; tr_body(W_memt, g_Wt3,        512, 1536, id % 16, id / 16); }
        return;
    }
    const int i = (id - 5888) * 256 + threadIdx.x;  // float4 index
    const int N1 = BATCH * 128;
    const int N2 = N1 + BATCH * 128;
    const float* src; __half* dst;
    size_t off;
    if (i < N1)      { off = (size_t)i << 2;        src = x;  dst = g_x16; }
    else if (i < N2) { off = (size_t)(i - N1) << 2; src = h;  dst = g_h16; }
    else             { off = (size_t)(i - N2) << 2; src = me; dst = g_me16; }
    const float4 v = *(const float4*)(src + off);
    const __half2 lo = __floats2half2_rn(v.x, v.y);
    const __half2 hi = __floats2half2_rn(v.z, v.w);
    uint2 u;
    u.x = *(const uint32_t*)&lo;
    u.y = *(const uint32_t*)&hi;
    *(uint2*)(dst + off) = u;
}

// ---------------- main GEMM ------------------------------------------------
// Tile 128x128, BK=64, 8 warps (2M x 4N), warp 64x32 = 4x4 m16n8k16 per kk.
// SMEM per stage: A[128][72] + B[128][72] halves, row 144B. 3 stages.
#define ROWB 144
#define TILE_B (128 * ROWB)
#define STAGE_B (2 * TILE_B)
#define SMEM_BYTES (3 * STAGE_B)    // 110592

template <int MODE>
__global__ void __launch_bounds__(256, 2) mma_gemm(
    const __half* __restrict__ A0, int lda0,
    const __half* __restrict__ A1, int lda1,
    int K0, int K,
    const __half* __restrict__ Wt,
    const float* __restrict__ bias,
    const float* __restrict__ me,
    const float* __restrict__ cin, const float* __restrict__ hin,
    float* __restrict__ outp)
{
    extern __shared__ char smem[];
    const uint32_t sbase = (uint32_t)__cvta_generic_to_shared(smem);
    const int tid = threadIdx.x, wid = tid >> 5, lane = tid & 31;
    const int bm = blockIdx.y << 7, bn = blockIdx.x << 7;
    const int wm = (wid >> 2) << 6;
    const int wn = (wid & 3) << 5;
    const int grp = lane >> 2, qd = lane & 3;

    float acc[4][4][4];
#pragma unroll
    for (int mt = 0; mt < 4; mt++)
#pragma unroll
        for (int nt = 0; nt < 4; nt++)
#pragma unroll
            for (int q = 0; q < 4; q++) acc[mt][nt][q] = 0.0f;

    const int nst = K >> 6;

    // ldmatrix per-lane byte offsets within a stage (kk adds 32B):
    const int l7 = lane & 7;
    const uint32_t a_off =
        (uint32_t)((wm + l7 + (((lane >> 3) & 1) << 3)) * ROWB) +
        (uint32_t)((((lane >> 4) & 1)) << 4);
    const uint32_t b_off = (uint32_t)TILE_B +
        (uint32_t)((wn + (((lane >> 4) & 1) << 3) + l7) * ROWB) +
        (uint32_t)((((lane >> 3) & 1)) << 4);

#define ISSUE_AB(S, BUF) do {                                                   \
    const int _k0 = (S) << 6;                                                   \
    _Pragma("unroll")                                                           \
    for (int t = 0; t < 4; t++) {                                               \
        const int i = tid + (t << 8);                                           \
        const int row = i >> 3, c16 = i & 7;                                    \
        const int ka = _k0 + (c16 << 3);                                        \
        const __half* pa = (ka < K0)                                            \
            ? A0 + (size_t)(bm + row) * lda0 + ka                               \
            : A1 + (size_t)(bm + row) * lda1 + (ka - K0);                       \
        const uint32_t dA = sbase +                                             \
            (uint32_t)((BUF) * STAGE_B + row * ROWB + (c16 << 4));              \
        CP_ASYNC16(dA, pa);                                                     \
        const uint32_t dB = sbase +                                             \
            (uint32_t)((BUF) * STAGE_B + TILE_B + row * ROWB + (c16 << 4));     \
        CP_ASYNC16(dB, Wt + (size_t)(bn + row) * K + ka);                       \
    }                                                                           \
    CP_COMMIT(); } while (0)

#define LDSM_B(BUFI, KK)                                                        \
    do {                                                                        \
        ldsm_x4(bf[BUFI][0], bf[BUFI][1], bf[BUFI][2], bf[BUFI][3],             \
                bbuf + (uint32_t)((KK) * 32));                                  \
        ldsm_x4(bf[BUFI][4], bf[BUFI][5], bf[BUFI][6], bf[BUFI][7],             \
                bbuf + (uint32_t)(16 * ROWB) + (uint32_t)((KK) * 32));          \
    } while (0)

    ISSUE_AB(0, 0);
    ISSUE_AB(1, 1);

    uint32_t bf[2][8];      // B fragments, double-buffered across kk

    int buf = 0;   // = s % 3
    for (int s = 0; s < nst; s++) {
        if (s + 1 < nst) CP_WAIT1(); else CP_WAIT0();
        __syncthreads();

        const uint32_t abuf = sbase + (uint32_t)(buf * STAGE_B) + a_off;
        const uint32_t bbuf = sbase + (uint32_t)(buf * STAGE_B) + b_off;

        // preload kk=0 B fragments; latency hides under cp.async issue burst
        LDSM_B(0, 0);
        if (s + 2 < nst) {
            const int wbuf = (buf + 2 >= 3) ? buf - 1 : buf + 2;
            ISSUE_AB(s + 2, wbuf);
        }

#pragma unroll
        for (int kk = 0; kk < 4; kk++) {              // 4 x k16 per BK=64
            uint32_t af[4][4];
#pragma unroll
            for (int mt = 0; mt < 4; mt++)
                ldsm_x4(af[mt][0], af[mt][1], af[mt][2], af[mt][3],
                        abuf + (uint32_t)(mt * (16 * ROWB)) + (uint32_t)(kk * 32));
            if (kk < 3) LDSM_B((kk + 1) & 1, kk + 1);  // prefetch next kk's B
            const int cb = kk & 1;
#pragma unroll
            for (int mt = 0; mt < 4; mt++)
#pragma unroll
                for (int nt = 0; nt < 4; nt++)
                    mma_f16(acc[mt][nt][0], acc[mt][nt][1],
                            acc[mt][nt][2], acc[mt][nt][3],
                            af[mt][0], af[mt][1], af[mt][2], af[mt][3],
                            bf[cb][2 * nt], bf[cb][2 * nt + 1]);
        }
        buf = (buf + 1 >= 3) ? 0 : buf + 1;
    }

    // ---- fused epilogues (c frag rows grp/grp+8, cols 2qd/2qd+1) ----
#pragma unroll
    for (int mt = 0; mt < 4; mt++) {
#pragma unroll
        for (int nt = 0; nt < 4; nt++) {
#pragma unroll
            for (int hrow = 0; hrow < 2; hrow++) {
                const int r = bm + wm + (mt << 4) + grp + (hrow << 3);
                const int cc = bn + wn + (nt << 3) + (qd << 1);
                const float v0 = acc[mt][nt][hrow * 2];
                const float v1 = acc[mt][nt][hrow * 2 + 1];
                if (MODE == 0) {
                    const float2 b2 = *(const float2*)(bias + cc);
                    float2 o = {v0 + b2.x, v1 + b2.y};
                    *(float2*)(g_gates + (size_t)r * 2048 + cc) = o;
                } else if (MODE == 1) {
                    const float2 b2 = *(const float2*)(bias + cc);
                    const float2 m2 = *(const float2*)(me + (size_t)r * 1536 + cc);
                    const __half2 o = __floats2half2_rn(sigf(v0 + b2.x) * m2.x,
                                                        sigf(v1 + b2.y) * m2.y);
                    *(__half2*)(g_s16 + (size_t)r * 1536 + cc) = o;
                } else {
                    const size_t gb = (size_t)r * 2048 + cc;
                    const float2 f2 = *(const float2*)(g_gates + gb);
                    const float2 i2 = *(const float2*)(g_gates + gb + 512);
                    const float2 o2 = *(const float2*)(g_gates + gb + 1024);
                    const float2 g2 = *(const float2*)(g_gates + gb + 1536);
                    const float2 c2 = *(const float2*)(cin + (size_t)r * 512 + cc);
                    const float2 h2 = *(const float2*)(hin + (size_t)r * 512 + cc);
                    float2 oh, oc;
                    {
                        float cn = sigf(f2.x) * c2.x + sigf(i2.x) * tanh_(g2.x) + v0;
                        float hn = sigf(o2.x) * tanh_(cn);
                        oh.x = 0.8f * hn + 0.2f * h2.x;
                        oc.x = 0.8f * cn + 0.2f * c2.x;
                    }
                    {
                        float cn = sigf(f2.y) * c2.y + sigf(i2.y) * tanh_(g2.y) + v1;
                        float hn = sigf(o2.y) * tanh_(cn);
                        oh.y = 0.8f * hn + 0.2f * h2.y;
                        oc.y = 0.8f * cn + 0.2f * c2.y;
                    }
                    *(float2*)(outp + (size_t)r * 512 + cc) = oh;
                    *(float2*)(outp + (size_t)BATCH * 512 + (size_t)r * 512 + cc) = oc;
                }
            }
        }
    }
}

// ---------------- host ----------------------------------------------------
extern "C" void kernel_launch(void* const* d_in, const int* in_sizes, int n_in,
                              void* d_out, int out_size)
{
    const float* x      = (const float*)d_in[0];
    const float* h      = (const float*)d_in[1];
    const float* c      = (const float*)d_in[2];
    const float* me     = (const float*)d_in[3];
    const float* W_ih   = (const float*)d_in[4];
    const float* W_hh   = (const float*)d_in[5];
    const float* bias   = (const float*)d_in[6];
    const float* W_memi = (const float*)d_in[7];
    const float* W_memh = (const float*)d_in[8];
    const float* W_memt = (const float*)d_in[9];
    const float* mem_b  = (const float*)d_in[10];
    float* out = (float*)d_out;

    cudaFuncSetAttribute(mma_gemm<0>, cudaFuncAttributeMaxDynamicSharedMemorySize, SMEM_BYTES);
    cudaFuncSetAttribute(mma_gemm<1>, cudaFuncAttributeMaxDynamicSharedMemorySize, SMEM_BYTES);
    cudaFuncSetAttribute(mma_gemm<2>, cudaFuncAttributeMaxDynamicSharedMemorySize, SMEM_BYTES);

    __half *wt1, *wt2, *wt3, *x16, *h16, *me16, *s16;
    cudaGetSymbolAddress((void**)&wt1, g_Wt1);
    cudaGetSymbolAddress((void**)&wt2, g_Wt2);
    cudaGetSymbolAddress((void**)&wt3, g_Wt3);
    cudaGetSymbolAddress((void**)&x16, g_x16);
    cudaGetSymbolAddress((void**)&h16, g_h16);
    cudaGetSymbolAddress((void**)&me16, g_me16);
    cudaGetSymbolAddress((void**)&s16, g_s16);

    prepass_all<<<5888 + (BATCH * 640) / 256, 256>>>(
        W_ih, W_hh, W_memi, W_memh, W_memt, x, h, me);

    mma_gemm<0><<<dim3(16, 128), 256, SMEM_BYTES>>>(
        x16, 512, h16, 512, 512, 1024, wt1, bias, nullptr, nullptr, nullptr, nullptr);

    mma_gemm<1><<<dim3(12, 128), 256, SMEM_BYTES>>>(
        x16, 512, me16, 1536, 512, 2048, wt2, mem_b, me, nullptr, nullptr, nullptr);

    mma_gemm<2><<<dim3(4, 128), 256, SMEM_BYTES>>>(
        s16, 1536, s16, 1536, 1536, 1536, wt3, nullptr, nullptr, c, h, out);
}

// round 17
// speedup vs baseline: 1.4373x; 1.0016x over previous
#include <cuda_runtime.h>
#include <cuda_fp16.h>
#include <cstdint>
#include <math.h>

// LSTMCell fused via mma.sync fp16 (m16n8k16, f32 accum) GEMMs.
//   gates = [x|h] @ Wt1^T + bias             (K=1024, N=2048)  -> fp16 scratch
//   s     = sigmoid([x|me] @ Wt2^T + mb)*me  (K=2048, N=1536)
//   t     = s @ Wt3^T ; LSTM epilogue        (K=1536, N=512)
// R12 skeleton (3-stage cp.async, BK=64, kk-level B prefetch) + fp16 gates.

#define BATCH 16384

// ---------------- scratch (__device__ globals: no allocations allowed) ----
__device__ __half g_gates[(size_t)BATCH * 2048];   // 64 MiB fp16 gate pre-acts
__device__ __half g_x16[(size_t)BATCH * 512];
__device__ __half g_h16[(size_t)BATCH * 512];
__device__ __half g_me16[(size_t)BATCH * 1536];
__device__ __half g_s16[(size_t)BATCH * 1536];
__device__ __half g_Wt1[(size_t)2048 * 1024];      // [n][k] K-major fp16
__device__ __half g_Wt2[(size_t)1536 * 2048];
__device__ __half g_Wt3[(size_t)512 * 1536];

__device__ __forceinline__ float sigf(float x) { return 1.0f / (1.0f + __expf(-x)); }
__device__ __forceinline__ float tanh_(float x) { return 2.0f * sigf(2.0f * x) - 1.0f; }

__device__ __forceinline__ void mma_f16(float& c0, float& c1, float& c2, float& c3,
                                        uint32_t a0, uint32_t a1, uint32_t a2, uint32_t a3,
                                        uint32_t b0, uint32_t b1) {
    asm volatile(
        "mma.sync.aligned.m16n8k16.row.col.f32.f16.f16.f32 "
        "{%0,%1,%2,%3}, {%4,%5,%6,%7}, {%8,%9}, {%0,%1,%2,%3};"
        : "+f"(c0), "+f"(c1), "+f"(c2), "+f"(c3)
        : "r"(a0), "r"(a1), "r"(a2), "r"(a3), "r"(b0), "r"(b1));
}

__device__ __forceinline__ void ldsm_x4(uint32_t& r0, uint32_t& r1,
                                        uint32_t& r2, uint32_t& r3, uint32_t addr) {
    asm volatile("ldmatrix.sync.aligned.m8n8.x4.shared.b16 {%0,%1,%2,%3}, [%4];"
                 : "=r"(r0), "=r"(r1), "=r"(r2), "=r"(r3) : "r"(addr));
}

#define CP_ASYNC16(dst_u32, src_ptr) \
    asm volatile("cp.async.cg.shared.global [%0], [%1], 16;" \
                 :: "r"(dst_u32), "l"(src_ptr))
#define CP_COMMIT() asm volatile("cp.async.commit_group;")
#define CP_WAIT1()  asm volatile("cp.async.wait_group 1;" ::: "memory")
#define CP_WAIT0()  asm volatile("cp.async.wait_group 0;" ::: "memory")

// ---------------- merged pre-pass: weight transpose + activation pack -----
__device__ __forceinline__ void tr_body(const float* __restrict__ src,
                                        __half* __restrict__ dst,
                                        int C, int dstStride, int bx, int by) {
    __shared__ float t[32][33];
    const int c0 = bx << 5, r0 = by << 5;
    const int tx = threadIdx.x & 31, ty = threadIdx.x >> 5;
#pragma unroll
    for (int j = ty; j < 32; j += 8)
        t[j][tx] = src[(size_t)(r0 + j) * C + c0 + tx];
    __syncthreads();
#pragma unroll
    for (int j = ty; j < 32; j += 8)
        dst[(size_t)(c0 + j) * dstStride + r0 + tx] = __float2half_rn(t[tx][j]);
}

// grid = 5888 transpose blocks + 40960 pack blocks (256 thr each)
__global__ void __launch_bounds__(256) prepass_all(
    const float* __restrict__ W_ih,  const float* __restrict__ W_hh,
    const float* __restrict__ W_memi, const float* __restrict__ W_memh,
    const float* __restrict__ W_memt,
    const float* __restrict__ x, const float* __restrict__ h,
    const float* __restrict__ me)
{
    int id = blockIdx.x;
    if (id < 5888) {
        if (id < 1024)      tr_body(W_ih,   g_Wt1,        2048, 1024, id % 64, id / 64);
        else if (id < 2048) { id -= 1024; tr_body(W_hh,   g_Wt1 + 512, 2048, 1024, id % 64, id / 64); }
        else if (id < 2816) { id -= 2048; tr_body(W_memi, g_Wt2,       1536, 2048, id % 48, id / 48); }
        else if (id < 5120) { id -= 2816; tr_body(W_memh, g_Wt2 + 512, 1536, 2048, id % 48, id / 48); }
        else                { id -= 5120; tr_body(W_memt, g_Wt3,        512, 1536, id % 16, id / 16); }
        return;
    }
    const int i = (id - 5888) * 256 + threadIdx.x;  // float4 index
    const int N1 = BATCH * 128;
    const int N2 = N1 + BATCH * 128;
    const float* src; __half* dst;
    size_t off;
    if (i < N1)      { off = (size_t)i << 2;        src = x;  dst = g_x16; }
    else if (i < N2) { off = (size_t)(i - N1) << 2; src = h;  dst = g_h16; }
    else             { off = (size_t)(i - N2) << 2; src = me; dst = g_me16; }
    const float4 v = *(const float4*)(src + off);
    const __half2 lo = __floats2half2_rn(v.x, v.y);
    const __half2 hi = __floats2half2_rn(v.z, v.w);
    uint2 u;
    u.x = *(const uint32_t*)&lo;
    u.y = *(const uint32_t*)&hi;
    *(uint2*)(dst + off) = u;
}

// ---------------- main GEMM ------------------------------------------------
// Tile 128x128, BK=64, 8 warps (2M x 4N), warp 64x32 = 4x4 m16n8k16 per kk.
// SMEM per stage: A[128][72] + B[128][72] halves, row 144B. 3 stages.
#define ROWB 144
#define TILE_B (128 * ROWB)
#define STAGE_B (2 * TILE_B)
#define SMEM_BYTES (3 * STAGE_B)    // 110592

template <int MODE>
__global__ void __launch_bounds__(256, 2) mma_gemm(
    const __half* __restrict__ A0, int lda0,
    const __half* __restrict__ A1, int lda1,
    int K0, int K,
    const __half* __restrict__ Wt,
    const float* __restrict__ bias,
    const float* __restrict__ me,
    const float* __restrict__ cin, const float* __restrict__ hin,
    float* __restrict__ outp)
{
    extern __shared__ char smem[];
    const uint32_t sbase = (uint32_t)__cvta_generic_to_shared(smem);
    const int tid = threadIdx.x, wid = tid >> 5, lane = tid & 31;
    const int bm = blockIdx.y << 7, bn = blockIdx.x << 7;
    const int wm = (wid >> 2) << 6;
    const int wn = (wid & 3) << 5;
    const int grp = lane >> 2, qd = lane & 3;

    float acc[4][4][4];
#pragma unroll
    for (int mt = 0; mt < 4; mt++)
#pragma unroll
        for (int nt = 0; nt < 4; nt++)
#pragma unroll
            for (int q = 0; q < 4; q++) acc[mt][nt][q] = 0.0f;

    const int nst = K >> 6;

    // ldmatrix per-lane byte offsets within a stage (kk adds 32B):
    const int l7 = lane & 7;
    const uint32_t a_off =
        (uint32_t)((wm + l7 + (((lane >> 3) & 1) << 3)) * ROWB) +
        (uint32_t)((((lane >> 4) & 1)) << 4);
    const uint32_t b_off = (uint32_t)TILE_B +
        (uint32_t)((wn + (((lane >> 4) & 1) << 3) + l7) * ROWB) +
        (uint32_t)((((lane >> 3) & 1)) << 4);

#define ISSUE_AB(S, BUF) do {                                                   \
    const int _k0 = (S) << 6;                                                   \
    _Pragma("unroll")                                                           \
    for (int t = 0; t < 4; t++) {                                               \
        const int i = tid + (t << 8);                                           \
        const int row = i >> 3, c16 = i & 7;                                    \
        const int ka = _k0 + (c16 << 3);                                        \
        const __half* pa = (ka < K0)                                            \
            ? A0 + (size_t)(bm + row) * lda0 + ka                               \
            : A1 + (size_t)(bm + row) * lda1 + (ka - K0);                       \
        const uint32_t dA = sbase +                                             \
            (uint32_t)((BUF) * STAGE_B + row * ROWB + (c16 << 4));              \
        CP_ASYNC16(dA, pa);                                                     \
        const uint32_t dB = sbase +                                             \
            (uint32_t)((BUF) * STAGE_B + TILE_B + row * ROWB + (c16 << 4));     \
        CP_ASYNC16(dB, Wt + (size_t)(bn + row) * K + ka);                       \
    }                                                                           \
    CP_COMMIT(); } while (0)

#define LDSM_B(BUFI, KK)                                                        \
    do {                                                                        \
        ldsm_x4(bf[BUFI][0], bf[BUFI][1], bf[BUFI][2], bf[BUFI][3],             \
                bbuf + (uint32_t)((KK) * 32));                                  \
        ldsm_x4(bf[BUFI][4], bf[BUFI][5], bf[BUFI][6], bf[BUFI][7],             \
                bbuf + (uint32_t)(16 * ROWB) + (uint32_t)((KK) * 32));          \
    } while (0)

    ISSUE_AB(0, 0);
    ISSUE_AB(1, 1);

    uint32_t bf[2][8];      // B fragments, double-buffered across kk

    int buf = 0;   // = s % 3
    for (int s = 0; s < nst; s++) {
        if (s + 1 < nst) CP_WAIT1(); else CP_WAIT0();
        __syncthreads();

        const uint32_t abuf = sbase + (uint32_t)(buf * STAGE_B) + a_off;
        const uint32_t bbuf = sbase + (uint32_t)(buf * STAGE_B) + b_off;

        // preload kk=0 B fragments; latency hides under cp.async issue burst
        LDSM_B(0, 0);
        if (s + 2 < nst) {
            const int wbuf = (buf + 2 >= 3) ? buf - 1 : buf + 2;
            ISSUE_AB(s + 2, wbuf);
        }

#pragma unroll
        for (int kk = 0; kk < 4; kk++) {              // 4 x k16 per BK=64
            uint32_t af[4][4];
#pragma unroll
            for (int mt = 0; mt < 4; mt++)
                ldsm_x4(af[mt][0], af[mt][1], af[mt][2], af[mt][3],
                        abuf + (uint32_t)(mt * (16 * ROWB)) + (uint32_t)(kk * 32));
            if (kk < 3) LDSM_B((kk + 1) & 1, kk + 1);  // prefetch next kk's B
            const int cb = kk & 1;
#pragma unroll
            for (int mt = 0; mt < 4; mt++)
#pragma unroll
                for (int nt = 0; nt < 4; nt++)
                    mma_f16(acc[mt][nt][0], acc[mt][nt][1],
                            acc[mt][nt][2], acc[mt][nt][3],
                            af[mt][0], af[mt][1], af[mt][2], af[mt][3],
                            bf[cb][2 * nt], bf[cb][2 * nt + 1]);
        }
        buf = (buf + 1 >= 3) ? 0 : buf + 1;
    }

    // ---- fused epilogues (c frag rows grp/grp+8, cols 2qd/2qd+1) ----
#pragma unroll
    for (int mt = 0; mt < 4; mt++) {
#pragma unroll
        for (int nt = 0; nt < 4; nt++) {
#pragma unroll
            for (int hrow = 0; hrow < 2; hrow++) {
                const int r = bm + wm + (mt << 4) + grp + (hrow << 3);
                const int cc = bn + wn + (nt << 3) + (qd << 1);
                const float v0 = acc[mt][nt][hrow * 2];
                const float v1 = acc[mt][nt][hrow * 2 + 1];
                if (MODE == 0) {
                    const float2 b2 = *(const float2*)(bias + cc);
                    const __half2 o = __floats2half2_rn(v0 + b2.x, v1 + b2.y);
                    *(__half2*)(g_gates + (size_t)r * 2048 + cc) = o;
                } else if (MODE == 1) {
                    const float2 b2 = *(const float2*)(bias + cc);
                    const float2 m2 = *(const float2*)(me + (size_t)r * 1536 + cc);
                    const __half2 o = __floats2half2_rn(sigf(v0 + b2.x) * m2.x,
                                                        sigf(v1 + b2.y) * m2.y);
                    *(__half2*)(g_s16 + (size_t)r * 1536 + cc) = o;
                } else {
                    const size_t gb = (size_t)r * 2048 + cc;
                    const float2 f2 = __half22float2(*(const __half2*)(g_gates + gb));
                    const float2 i2 = __half22float2(*(const __half2*)(g_gates + gb + 512));
                    const float2 o2 = __half22float2(*(const __half2*)(g_gates + gb + 1024));
                    const float2 g2 = __half22float2(*(const __half2*)(g_gates + gb + 1536));
                    const float2 c2 = *(const float2*)(cin + (size_t)r * 512 + cc);
                    const float2 h2 = *(const float2*)(hin + (size_t)r * 512 + cc);
                    float2 oh, oc;
                    {
                        float cn = sigf(f2.x) * c2.x + sigf(i2.x) * tanh_(g2.x) + v0;
                        float hn = sigf(o2.x) * tanh_(cn);
                        oh.x = 0.8f * hn + 0.2f * h2.x;
                        oc.x = 0.8f * cn + 0.2f * c2.x;
                    }
                    {
                        float cn = sigf(f2.y) * c2.y + sigf(i2.y) * tanh_(g2.y) + v1;
                        float hn = sigf(o2.y) * tanh_(cn);
                        oh.y = 0.8f * hn + 0.2f * h2.y;
                        oc.y = 0.8f * cn + 0.2f * c2.y;
                    }
                    *(float2*)(outp + (size_t)r * 512 + cc) = oh;
                    *(float2*)(outp + (size_t)BATCH * 512 + (size_t)r * 512 + cc) = oc;
                }
            }
        }
    }
}

// ---------------- host ----------------------------------------------------
extern "C" void kernel_launch(void* const* d_in, const int* in_sizes, int n_in,
                              void* d_out, int out_size)
{
    const float* x      = (const float*)d_in[0];
    const float* h      = (const float*)d_in[1];
    const float* c      = (const float*)d_in[2];
    const float* me     = (const float*)d_in[3];
    const float* W_ih   = (const float*)d_in[4];
    const float* W_hh   = (const float*)d_in[5];
    const float* bias   = (const float*)d_in[6];
    const float* W_memi = (const float*)d_in[7];
    const float* W_memh = (const float*)d_in[8];
    const float* W_memt = (const float*)d_in[9];
    const float* mem_b  = (const float*)d_in[10];
    float* out = (float*)d_out;

    cudaFuncSetAttribute(mma_gemm<0>, cudaFuncAttributeMaxDynamicSharedMemorySize, SMEM_BYTES);
    cudaFuncSetAttribute(mma_gemm<1>, cudaFuncAttributeMaxDynamicSharedMemorySize, SMEM_BYTES);
    cudaFuncSetAttribute(mma_gemm<2>, cudaFuncAttributeMaxDynamicSharedMemorySize, SMEM_BYTES);

    __half *wt1, *wt2, *wt3, *x16, *h16, *me16, *s16;
    cudaGetSymbolAddress((void**)&wt1, g_Wt1);
    cudaGetSymbolAddress((void**)&wt2, g_Wt2);
    cudaGetSymbolAddress((void**)&wt3, g_Wt3);
    cudaGetSymbolAddress((void**)&x16, g_x16);
    cudaGetSymbolAddress((void**)&h16, g_h16);
    cudaGetSymbolAddress((void**)&me16, g_me16);
    cudaGetSymbolAddress((void**)&s16, g_s16);

    prepass_all<<<5888 + (BATCH * 640) / 256, 256>>>(
        W_ih, W_hh, W_memi, W_memh, W_memt, x, h, me);

    mma_gemm<0><<<dim3(16, 128), 256, SMEM_BYTES>>>(
        x16, 512, h16, 512, 512, 1024, wt1, bias, nullptr, nullptr, nullptr, nullptr);

    mma_gemm<1><<<dim3(12, 128), 256, SMEM_BYTES>>>(
        x16, 512, me16, 1536, 512, 2048, wt2, mem_b, me, nullptr, nullptr, nullptr);

    mma_gemm<2><<<dim3(4, 128), 256, SMEM_BYTES>>>(
        s16, 1536, s16, 1536, 1536, 1536, wt3, nullptr, nullptr, c, h, out);
}